// round 13
// baseline (speedup 1.0000x reference)
#include <cuda_runtime.h>
#include <cuda_fp16.h>

#define HID 128
#define OUT_COLS 264
#define MAXN 50176

typedef unsigned long long ull;
typedef unsigned int uint;

// fp16 storage of projected node features (half2 packed as uint)
__device__ uint g_Pn[(size_t)MAXN * 64];   // x_nbr  @ W1[:128]
__device__ uint g_Pa[(size_t)MAXN * 64];   // x_agent@ W1[128:] + b1

// ---- packed fp32x2 helpers (sm_103a) --------------------------------------
__device__ __forceinline__ ull pack2(float lo, float hi) {
    ull r; asm("mov.b64 %0, {%1,%2};" : "=l"(r) : "f"(lo), "f"(hi)); return r;
}
__device__ __forceinline__ void ffma2(ull& d, ull a, ull b) {
    asm("fma.rn.f32x2 %0, %1, %2, %0;" : "+l"(d) : "l"(a), "l"(b));
}
__device__ __forceinline__ ull add2(ull a, ull b) {
    ull r; asm("add.rn.f32x2 %0, %1, %2;" : "=l"(r) : "l"(a), "l"(b)); return r;
}
__device__ __forceinline__ float2 unpack2(ull v) {
    float2 r; asm("mov.b64 {%0,%1}, %2;" : "=f"(r.x), "=f"(r.y) : "l"(v)); return r;
}
__device__ __forceinline__ uint h2u(__half2 h) { return *reinterpret_cast<uint*>(&h); }
__device__ __forceinline__ __half2 u2h(uint u) { return *reinterpret_cast<__half2*>(&u); }

// ---------------------------------------------------------------------------
// P[N,128] = X[N,128] @ W[128,128] (+bias), stored fp16 (R11, unchanged).
__global__ __launch_bounds__(256, 2) void gemm_x128(
    const float* __restrict__ X0, const float* __restrict__ X1,
    const float* __restrict__ W1, const float* __restrict__ b1,
    int N0, int N1)
{
    extern __shared__ char smraw[];
    ull*   ws2 = (ull*)smraw;                       // [64][128] pairs
    float* xs  = (float*)(smraw + 64 * 128 * 8);    // [64][132]
    const int t = threadIdx.x;
    const int sel = blockIdx.y;
    const float* __restrict__ X = sel ? X1 : X0;
    const float* __restrict__ W = sel ? (W1 + 128 * 128) : W1;
    uint* __restrict__ P = sel ? g_Pa : g_Pn;
    const int N = sel ? N1 : N0;
    const int row0 = blockIdx.x * 64;
    if (row0 >= N) return;

    for (int i = t; i < 64 * 128; i += 256) {
        int kp = i >> 7, c = i & 127;
        ws2[i] = pack2(W[(2 * kp) * 128 + c], W[(2 * kp + 1) * 128 + c]);
    }
    for (int i = t; i < 64 * 32; i += 256) {
        int r = i >> 5, c4 = i & 31;
        float4 v = make_float4(0.f, 0.f, 0.f, 0.f);
        int gr = row0 + r;
        if (gr < N) v = ((const float4*)X)[(size_t)gr * 32 + c4];
        float* xr = xs + r * 132 + c4 * 4;
        xr[0] = v.x; xr[1] = v.y; xr[2] = v.z; xr[3] = v.w;
    }
    __syncthreads();

    const int c  = (t & 31) * 4;
    const int r0 = (t >> 5) * 8;
    ull acc[8][4];
#pragma unroll
    for (int i = 0; i < 8; i++)
#pragma unroll
        for (int j = 0; j < 4; j++) acc[i][j] = 0ull;

#pragma unroll 4
    for (int kp = 0; kp < 64; kp++) {
        ull b2v[4];
        {
            ulonglong2 w0 = *(const ulonglong2*)(ws2 + kp * 128 + c);
            ulonglong2 w1 = *(const ulonglong2*)(ws2 + kp * 128 + c + 2);
            b2v[0] = w0.x; b2v[1] = w0.y; b2v[2] = w1.x; b2v[3] = w1.y;
        }
#pragma unroll
        for (int i = 0; i < 8; i++) {
            ull a2 = *(const ull*)(xs + (r0 + i) * 132 + kp * 2);
            ffma2(acc[i][0], a2, b2v[0]);
            ffma2(acc[i][1], a2, b2v[1]);
            ffma2(acc[i][2], a2, b2v[2]);
            ffma2(acc[i][3], a2, b2v[3]);
        }
    }

    float bvx = 0.f, bvy = 0.f, bvz = 0.f, bvw = 0.f;
    if (sel) { float4 bb = *(const float4*)(b1 + c);
               bvx = bb.x; bvy = bb.y; bvz = bb.z; bvw = bb.w; }
#pragma unroll
    for (int i = 0; i < 8; i++) {
        int gr = row0 + r0 + i;
        if (gr < N) {
            float2 u0 = unpack2(acc[i][0]), u1 = unpack2(acc[i][1]);
            float2 u2 = unpack2(acc[i][2]), u3 = unpack2(acc[i][3]);
            uint p01 = h2u(__floats2half2_rn(u0.x + u0.y + bvx, u1.x + u1.y + bvy));
            uint p23 = h2u(__floats2half2_rn(u2.x + u2.y + bvz, u3.x + u3.y + bvw));
            *(uint2*)(P + (size_t)gr * 64 + (c >> 1)) = make_uint2(p01, p23);
        }
    }
}

// ---------------------------------------------------------------------------
// Two-phase fused edge kernel v3. Block = 256 threads, 256 edges = 16 agents.
// Phase 1: gather+relu -> v_sm (dynamic, 64KB), XOR swizzle 2*(el&15);
//          stage (dst,slot) into dssm.
// Phase 2: thread (ep, h) handles edges {ep, ep+128}, cols 4h..4h+3.
//          One weight fetch per k-pair-pair feeds 2 edges x 2 kp of FFMA2;
//          activations via uint2 (conflict-free; (ep+128)&15 == ep&15).
// Plus zero out[:,128:256) and own-score for the block's 16 agents.
__global__ __launch_bounds__(256) void edge_fused_kernel(
    const float* __restrict__ W2, const float* __restrict__ b2,
    const float* __restrict__ Wa, const float* __restrict__ ba,
    const float* __restrict__ xa,
    const void* __restrict__ esrc, const void* __restrict__ edst,
    const void* __restrict__ eslot,
    float* __restrict__ out, int E, int Na)
{
    extern __shared__ uint v_sm[];       // [256][64] uints = 64 KB dynamic
    __shared__ ull   w2p[64 * 8];        // (even,odd) k-pair packed W2
    __shared__ float was[32 * 36];       // own-score weights, stride-36 layout
    __shared__ int2  dssm[256];          // (dst, slot) per edge
    __shared__ float b2s[8], bas[8];

    const int t = threadIdx.x;

    for (int i = t; i < 512; i += 256) {
        int kp = i >> 3, c = i & 7;
        w2p[i] = pack2(W2[(2 * kp) * 8 + c], W2[(2 * kp + 1) * 8 + c]);
    }
    for (int i = t; i < 1024; i += 256) {
        int k = i >> 3, c = i & 7;
        was[(k >> 2) * 36 + (k & 3) * 8 + c] = Wa[i];
    }
    if (t < 8) { b2s[t] = b2[t]; bas[t] = ba[t]; }

    const int idx64 = (((const int*)eslot)[1] != 1);
    const int e0 = blockIdx.x * 256;
    const __half2 z2 = __floats2half2_rn(0.f, 0.f);

    // ---- phase 1: gather + relu -> v_sm, stage dst/slot -------------------
    {
        const int j  = t & 7;
        const int eb = t >> 3;           // 0..31
#pragma unroll
        for (int s = 0; s < 8; s++) {
            int el = eb + 32 * s;
            int eg = e0 + el;
            if (eg < E) {
                int src, dst, slot;
                if (idx64) { src  = ((const int*)esrc)[2 * eg];
                             dst  = ((const int*)edst)[2 * eg];
                             slot = ((const int*)eslot)[2 * eg]; }
                else       { src  = ((const int*)esrc)[eg];
                             dst  = ((const int*)edst)[eg];
                             slot = ((const int*)eslot)[eg]; }
                if (j == 0) dssm[el] = make_int2(dst, slot);

                const uint4* pr = (const uint4*)(g_Pn + (size_t)src * 64);
                const uint4* ar = (const uint4*)(g_Pa + (size_t)dst * 64);
                uint4 A0 = pr[j], A1 = pr[j + 8];
                uint4 C0 = ar[j], C1 = ar[j + 8];
                uint4 V0, V1;
                V0.x = h2u(__hmax2(__hadd2(u2h(A0.x), u2h(C0.x)), z2));
                V0.y = h2u(__hmax2(__hadd2(u2h(A0.y), u2h(C0.y)), z2));
                V0.z = h2u(__hmax2(__hadd2(u2h(A0.z), u2h(C0.z)), z2));
                V0.w = h2u(__hmax2(__hadd2(u2h(A0.w), u2h(C0.w)), z2));
                V1.x = h2u(__hmax2(__hadd2(u2h(A1.x), u2h(C1.x)), z2));
                V1.y = h2u(__hmax2(__hadd2(u2h(A1.y), u2h(C1.y)), z2));
                V1.z = h2u(__hmax2(__hadd2(u2h(A1.z), u2h(C1.z)), z2));
                V1.w = h2u(__hmax2(__hadd2(u2h(A1.w), u2h(C1.w)), z2));

                const int xr = 2 * (el & 15);
                uint* vb = v_sm + el * 64;
                int q0 = (4 * j) ^ xr;
                *(uint2*)(vb + q0)       = make_uint2(V0.x, V0.y);
                *(uint2*)(vb + (q0 ^ 2)) = make_uint2(V0.z, V0.w);
                int q1 = q0 + 32;
                *(uint2*)(vb + q1)       = make_uint2(V1.x, V1.y);
                *(uint2*)(vb + (q1 ^ 2)) = make_uint2(V1.z, V1.w);
            }
        }
    }
    __syncthreads();

    // ---- phase 2: matvec, 2 edges per thread ------------------------------
    {
        const int ep = t >> 1;           // 0..127
        const int h  = t & 1;            // cols 4h..4h+3
        const int xr = 2 * (ep & 15);    // same for ep and ep+128
        const uint* vb0 = v_sm + ep * 64;
        const uint* vb1 = v_sm + (ep + 128) * 64;

        ull acc0[4] = {0ull, 0ull, 0ull, 0ull};
        ull acc1[4] = {0ull, 0ull, 0ull, 0ull};

#pragma unroll 8
        for (int kp = 0; kp < 64; kp += 2) {
            // weights for k-pairs kp, kp+1 (cols 4h..4h+3): 4 LDS.128
            const ull* wa_ = w2p + kp * 8 + 4 * h;
            const ull* wb_ = w2p + (kp + 1) * 8 + 4 * h;
            ulonglong2 wA0 = *(const ulonglong2*)wa_;
            ulonglong2 wA1 = *(const ulonglong2*)(wa_ + 2);
            ulonglong2 wB0 = *(const ulonglong2*)wb_;
            ulonglong2 wB1 = *(const ulonglong2*)(wb_ + 2);
            // activations: 2 k-pairs per edge via one uint2
            uint2 va = *(const uint2*)(vb0 + (kp ^ xr));
            uint2 vc = *(const uint2*)(vb1 + (kp ^ xr));

            float2 f;
            f = __half22float2(u2h(va.x)); ull v0 = pack2(f.x, f.y);
            ffma2(acc0[0], v0, wA0.x); ffma2(acc0[1], v0, wA0.y);
            ffma2(acc0[2], v0, wA1.x); ffma2(acc0[3], v0, wA1.y);
            f = __half22float2(u2h(va.y)); ull v1 = pack2(f.x, f.y);
            ffma2(acc0[0], v1, wB0.x); ffma2(acc0[1], v1, wB0.y);
            ffma2(acc0[2], v1, wB1.x); ffma2(acc0[3], v1, wB1.y);

            f = __half22float2(u2h(vc.x)); ull u0 = pack2(f.x, f.y);
            ffma2(acc1[0], u0, wA0.x); ffma2(acc1[1], u0, wA0.y);
            ffma2(acc1[2], u0, wA1.x); ffma2(acc1[3], u0, wA1.y);
            f = __half22float2(u2h(vc.y)); ull u1 = pack2(f.x, f.y);
            ffma2(acc1[0], u1, wB0.x); ffma2(acc1[1], u1, wB0.y);
            ffma2(acc1[2], u1, wB1.x); ffma2(acc1[3], u1, wB1.y);
        }

        if (e0 + ep < E) {
            int2 ds = dssm[ep];
            float2 u0 = unpack2(acc0[0]), u1 = unpack2(acc0[1]);
            float2 u2 = unpack2(acc0[2]), u3 = unpack2(acc0[3]);
            float4 r = make_float4(u0.x + u0.y + b2s[4 * h],
                                   u1.x + u1.y + b2s[4 * h + 1],
                                   u2.x + u2.y + b2s[4 * h + 2],
                                   u3.x + u3.y + b2s[4 * h + 3]);
            *(float4*)(out + (size_t)ds.x * OUT_COLS + ds.y * 8 + 4 * h) = r;
        }
        if (e0 + ep + 128 < E) {
            int2 ds = dssm[ep + 128];
            float2 u0 = unpack2(acc1[0]), u1 = unpack2(acc1[1]);
            float2 u2 = unpack2(acc1[2]), u3 = unpack2(acc1[3]);
            float4 r = make_float4(u0.x + u0.y + b2s[4 * h],
                                   u1.x + u1.y + b2s[4 * h + 1],
                                   u2.x + u2.y + b2s[4 * h + 2],
                                   u3.x + u3.y + b2s[4 * h + 3]);
            *(float4*)(out + (size_t)ds.x * OUT_COLS + ds.y * 8 + 4 * h) = r;
        }
    }

    // ---- zero out[:,128:256) for this block's 16 agents -------------------
    const int ag0 = blockIdx.x * 16;
    {
        float4 z = make_float4(0.f, 0.f, 0.f, 0.f);
#pragma unroll
        for (int i = t; i < 512; i += 256) {
            int a = ag0 + (i >> 5);
            if (a < Na)
                *(float4*)(out + (size_t)a * OUT_COLS + 128 + (i & 31) * 4) = z;
        }
    }

    // ---- own scores: threads 0..127, 8 threads per agent ------------------
    if (t < 128) {
        int a  = ag0 + (t >> 3);
        int jj = t & 7;
        if (a < Na) {
            const float4* xr4 = (const float4*)(xa + (size_t)a * 128);
            float4 a4[4];
#pragma unroll
            for (int i = 0; i < 4; i++) a4[i] = xr4[jj + 8 * i];

            ull acc[4] = {0ull, 0ull, 0ull, 0ull};
#pragma unroll
            for (int i = 0; i < 4; i++) {
                const float* wb = was + (jj + 8 * i) * 36;
#pragma unroll
                for (int q = 0; q < 4; q++) {
                    float v = (q == 0) ? a4[i].x : (q == 1) ? a4[i].y
                            : (q == 2) ? a4[i].z : a4[i].w;
                    ull vv = pack2(v, v);
                    const ull* w = (const ull*)(wb + q * 8);
                    ffma2(acc[0], vv, w[0]);
                    ffma2(acc[1], vv, w[1]);
                    ffma2(acc[2], vv, w[2]);
                    ffma2(acc[3], vv, w[3]);
                }
            }
#pragma unroll
            for (int d = 1; d < 8; d <<= 1) {
#pragma unroll
                for (int p = 0; p < 4; p++)
                    acc[p] = add2(acc[p], __shfl_xor_sync(0xffffffffu, acc[p], d));
            }
            float2 u = unpack2(acc[jj >> 1]);
            float s = ((jj & 1) ? u.y : u.x) + bas[jj];
            out[(size_t)a * OUT_COLS + 256 + jj] = s;
        }
    }
}

// ---------------------------------------------------------------------------
extern "C" void kernel_launch(void* const* d_in, const int* in_sizes, int n_in,
                              void* d_out, int out_size)
{
    const float* x_nbr   = (const float*)d_in[0];
    const float* x_agent = (const float*)d_in[1];
    const float* W1      = (const float*)d_in[2];
    const float* b1      = (const float*)d_in[3];
    const float* W2      = (const float*)d_in[4];
    const float* b2      = (const float*)d_in[5];
    const float* Wa      = (const float*)d_in[6];
    const float* ba      = (const float*)d_in[7];
    const void*  esrc    = d_in[8];
    const void*  edst    = d_in[9];
    const void*  eslot   = d_in[10];

    int Nn = in_sizes[0] / HID;
    int Na = in_sizes[1] / HID;
    int E  = in_sizes[8];
    float* out = (float*)d_out;

    const int gemm_smem = 64 * 128 * 8 + 64 * 132 * 4;   // 99328 B
    cudaFuncSetAttribute(gemm_x128, cudaFuncAttributeMaxDynamicSharedMemorySize,
                         gemm_smem);
    const int edge_smem = 256 * 64 * 4;                  // 65536 B dynamic
    cudaFuncSetAttribute(edge_fused_kernel,
                         cudaFuncAttributeMaxDynamicSharedMemorySize, edge_smem);

    int Nmax = Nn > Na ? Nn : Na;
    dim3 ggrid((Nmax + 63) / 64, 2);
    gemm_x128<<<ggrid, 256, gemm_smem>>>(x_nbr, x_agent, W1, b1, Nn, Na);

    int blocks_e = (E + 255) / 256;
    int blocks_a = (Na + 15) / 16;
    int blocks = blocks_e > blocks_a ? blocks_e : blocks_a;
    edge_fused_kernel<<<blocks, 256, edge_smem>>>(W2, b2, Wa, ba, x_agent,
                                                  esrc, edst, eslot, out, E, Na);
}

// round 14
// speedup vs baseline: 1.0556x; 1.0556x over previous
#include <cuda_runtime.h>
#include <cuda_fp16.h>

#define HID 128
#define OUT_COLS 264
#define MAXN 50176

typedef unsigned long long ull;
typedef unsigned int uint;

// fp16 storage of projected node features (half2 packed as uint)
__device__ uint g_Pn[(size_t)MAXN * 64];   // x_nbr  @ W1[:128]
__device__ uint g_Pa[(size_t)MAXN * 64];   // x_agent@ W1[128:] + b1

// ---- packed fp32x2 helpers (sm_103a) --------------------------------------
__device__ __forceinline__ ull pack2(float lo, float hi) {
    ull r; asm("mov.b64 %0, {%1,%2};" : "=l"(r) : "f"(lo), "f"(hi)); return r;
}
__device__ __forceinline__ void ffma2(ull& d, ull a, ull b) {
    asm("fma.rn.f32x2 %0, %1, %2, %0;" : "+l"(d) : "l"(a), "l"(b));
}
__device__ __forceinline__ ull add2(ull a, ull b) {
    ull r; asm("add.rn.f32x2 %0, %1, %2;" : "=l"(r) : "l"(a), "l"(b)); return r;
}
__device__ __forceinline__ float2 unpack2(ull v) {
    float2 r; asm("mov.b64 {%0,%1}, %2;" : "=f"(r.x), "=f"(r.y) : "l"(v)); return r;
}
__device__ __forceinline__ uint h2u(__half2 h) { return *reinterpret_cast<uint*>(&h); }
__device__ __forceinline__ __half2 u2h(uint u) { return *reinterpret_cast<__half2*>(&u); }

// ---------------------------------------------------------------------------
// P[N,128] = X[N,128] @ W[128,128] (+bias), stored fp16 (R11, unchanged).
__global__ __launch_bounds__(256, 2) void gemm_x128(
    const float* __restrict__ X0, const float* __restrict__ X1,
    const float* __restrict__ W1, const float* __restrict__ b1,
    int N0, int N1)
{
    extern __shared__ char smraw[];
    ull*   ws2 = (ull*)smraw;                       // [64][128] pairs
    float* xs  = (float*)(smraw + 64 * 128 * 8);    // [64][132]
    const int t = threadIdx.x;
    const int sel = blockIdx.y;
    const float* __restrict__ X = sel ? X1 : X0;
    const float* __restrict__ W = sel ? (W1 + 128 * 128) : W1;
    uint* __restrict__ P = sel ? g_Pa : g_Pn;
    const int N = sel ? N1 : N0;
    const int row0 = blockIdx.x * 64;
    if (row0 >= N) return;

    for (int i = t; i < 64 * 128; i += 256) {
        int kp = i >> 7, c = i & 127;
        ws2[i] = pack2(W[(2 * kp) * 128 + c], W[(2 * kp + 1) * 128 + c]);
    }
    for (int i = t; i < 64 * 32; i += 256) {
        int r = i >> 5, c4 = i & 31;
        float4 v = make_float4(0.f, 0.f, 0.f, 0.f);
        int gr = row0 + r;
        if (gr < N) v = ((const float4*)X)[(size_t)gr * 32 + c4];
        float* xr = xs + r * 132 + c4 * 4;
        xr[0] = v.x; xr[1] = v.y; xr[2] = v.z; xr[3] = v.w;
    }
    __syncthreads();

    const int c  = (t & 31) * 4;
    const int r0 = (t >> 5) * 8;
    ull acc[8][4];
#pragma unroll
    for (int i = 0; i < 8; i++)
#pragma unroll
        for (int j = 0; j < 4; j++) acc[i][j] = 0ull;

#pragma unroll 4
    for (int kp = 0; kp < 64; kp++) {
        ull b2v[4];
        {
            ulonglong2 w0 = *(const ulonglong2*)(ws2 + kp * 128 + c);
            ulonglong2 w1 = *(const ulonglong2*)(ws2 + kp * 128 + c + 2);
            b2v[0] = w0.x; b2v[1] = w0.y; b2v[2] = w1.x; b2v[3] = w1.y;
        }
#pragma unroll
        for (int i = 0; i < 8; i++) {
            ull a2 = *(const ull*)(xs + (r0 + i) * 132 + kp * 2);
            ffma2(acc[i][0], a2, b2v[0]);
            ffma2(acc[i][1], a2, b2v[1]);
            ffma2(acc[i][2], a2, b2v[2]);
            ffma2(acc[i][3], a2, b2v[3]);
        }
    }

    float bvx = 0.f, bvy = 0.f, bvz = 0.f, bvw = 0.f;
    if (sel) { float4 bb = *(const float4*)(b1 + c);
               bvx = bb.x; bvy = bb.y; bvz = bb.z; bvw = bb.w; }
#pragma unroll
    for (int i = 0; i < 8; i++) {
        int gr = row0 + r0 + i;
        if (gr < N) {
            float2 u0 = unpack2(acc[i][0]), u1 = unpack2(acc[i][1]);
            float2 u2 = unpack2(acc[i][2]), u3 = unpack2(acc[i][3]);
            uint p01 = h2u(__floats2half2_rn(u0.x + u0.y + bvx, u1.x + u1.y + bvy));
            uint p23 = h2u(__floats2half2_rn(u2.x + u2.y + bvz, u3.x + u3.y + bvw));
            *(uint2*)(P + (size_t)gr * 64 + (c >> 1)) = make_uint2(p01, p23);
        }
    }
}

// ---------------------------------------------------------------------------
// Two-phase fused edge kernel v4. Block = 512 threads, 256 edges = 16 agents.
// Phase 1 (all 512): gather+relu -> v_sm (64KB dyn), XOR swizzle 2*(el&15);
//                    stage (dst,slot).
// Phase 2 splits the block:
//   t <  256: matvec, thread (ep,h) handles edges {ep, ep+128}, cols 4h..4h+3.
//             One weight fetch per k-pair-pair feeds 2 edges x 2 kp (R13 body).
//   t >= 256: zero out[:,128:256) + own-score out[:,256:264) for the 16 agents
//             (runs concurrently with the matvec warps -> latency hiding).
__global__ __launch_bounds__(512, 2) void edge_fused_kernel(
    const float* __restrict__ W2, const float* __restrict__ b2,
    const float* __restrict__ Wa, const float* __restrict__ ba,
    const float* __restrict__ xa,
    const void* __restrict__ esrc, const void* __restrict__ edst,
    const void* __restrict__ eslot,
    float* __restrict__ out, int E, int Na)
{
    extern __shared__ uint v_sm[];       // [256][64] uints = 64 KB dynamic
    __shared__ ull   w2p[64 * 8];        // (even,odd) k-pair packed W2
    __shared__ float was[32 * 36];       // own-score weights, stride-36 layout
    __shared__ int2  dssm[256];          // (dst, slot) per edge
    __shared__ float b2s[8], bas[8];

    const int t = threadIdx.x;

    for (int i = t; i < 512; i += 512) {
        int kp = i >> 3, c = i & 7;
        w2p[i] = pack2(W2[(2 * kp) * 8 + c], W2[(2 * kp + 1) * 8 + c]);
    }
    for (int i = t; i < 1024; i += 512) {
        int k = i >> 3, c = i & 7;
        was[(k >> 2) * 36 + (k & 3) * 8 + c] = Wa[i];
    }
    if (t < 8) { b2s[t] = b2[t]; bas[t] = ba[t]; }

    const int idx64 = (((const int*)eslot)[1] != 1);
    const int e0 = blockIdx.x * 256;
    const int ag0 = blockIdx.x * 16;
    const __half2 z2 = __floats2half2_rn(0.f, 0.f);

    // ---- phase 1: gather + relu -> v_sm, stage dst/slot (all 512) ---------
    {
        const int j  = t & 7;
        const int eb = t >> 3;           // 0..63
#pragma unroll
        for (int s = 0; s < 4; s++) {
            int el = eb + 64 * s;
            int eg = e0 + el;
            if (eg < E) {
                int src, dst, slot;
                if (idx64) { src  = ((const int*)esrc)[2 * eg];
                             dst  = ((const int*)edst)[2 * eg];
                             slot = ((const int*)eslot)[2 * eg]; }
                else       { src  = ((const int*)esrc)[eg];
                             dst  = ((const int*)edst)[eg];
                             slot = ((const int*)eslot)[eg]; }
                if (j == 0) dssm[el] = make_int2(dst, slot);

                const uint4* pr = (const uint4*)(g_Pn + (size_t)src * 64);
                const uint4* ar = (const uint4*)(g_Pa + (size_t)dst * 64);
                uint4 A0 = pr[j], A1 = pr[j + 8];
                uint4 C0 = ar[j], C1 = ar[j + 8];
                uint4 V0, V1;
                V0.x = h2u(__hmax2(__hadd2(u2h(A0.x), u2h(C0.x)), z2));
                V0.y = h2u(__hmax2(__hadd2(u2h(A0.y), u2h(C0.y)), z2));
                V0.z = h2u(__hmax2(__hadd2(u2h(A0.z), u2h(C0.z)), z2));
                V0.w = h2u(__hmax2(__hadd2(u2h(A0.w), u2h(C0.w)), z2));
                V1.x = h2u(__hmax2(__hadd2(u2h(A1.x), u2h(C1.x)), z2));
                V1.y = h2u(__hmax2(__hadd2(u2h(A1.y), u2h(C1.y)), z2));
                V1.z = h2u(__hmax2(__hadd2(u2h(A1.z), u2h(C1.z)), z2));
                V1.w = h2u(__hmax2(__hadd2(u2h(A1.w), u2h(C1.w)), z2));

                const int xr = 2 * (el & 15);
                uint* vb = v_sm + el * 64;
                int q0 = (4 * j) ^ xr;
                *(uint2*)(vb + q0)       = make_uint2(V0.x, V0.y);
                *(uint2*)(vb + (q0 ^ 2)) = make_uint2(V0.z, V0.w);
                int q1 = q0 + 32;
                *(uint2*)(vb + q1)       = make_uint2(V1.x, V1.y);
                *(uint2*)(vb + (q1 ^ 2)) = make_uint2(V1.z, V1.w);
            }
        }
    }
    __syncthreads();

    if (t < 256) {
        // ---- phase 2: matvec, 2 edges per thread --------------------------
        const int ep = t >> 1;           // 0..127
        const int h  = t & 1;            // cols 4h..4h+3
        const int xr = 2 * (ep & 15);    // same for ep and ep+128
        const uint* vb0 = v_sm + ep * 64;
        const uint* vb1 = v_sm + (ep + 128) * 64;

        ull acc0[4] = {0ull, 0ull, 0ull, 0ull};
        ull acc1[4] = {0ull, 0ull, 0ull, 0ull};

#pragma unroll 8
        for (int kp = 0; kp < 64; kp += 2) {
            const ull* wa_ = w2p + kp * 8 + 4 * h;
            const ull* wb_ = w2p + (kp + 1) * 8 + 4 * h;
            ulonglong2 wA0 = *(const ulonglong2*)wa_;
            ulonglong2 wA1 = *(const ulonglong2*)(wa_ + 2);
            ulonglong2 wB0 = *(const ulonglong2*)wb_;
            ulonglong2 wB1 = *(const ulonglong2*)(wb_ + 2);
            uint2 va = *(const uint2*)(vb0 + (kp ^ xr));
            uint2 vc = *(const uint2*)(vb1 + (kp ^ xr));

            float2 f;
            f = __half22float2(u2h(va.x)); ull v0 = pack2(f.x, f.y);
            ffma2(acc0[0], v0, wA0.x); ffma2(acc0[1], v0, wA0.y);
            ffma2(acc0[2], v0, wA1.x); ffma2(acc0[3], v0, wA1.y);
            f = __half22float2(u2h(va.y)); ull v1 = pack2(f.x, f.y);
            ffma2(acc0[0], v1, wB0.x); ffma2(acc0[1], v1, wB0.y);
            ffma2(acc0[2], v1, wB1.x); ffma2(acc0[3], v1, wB1.y);

            f = __half22float2(u2h(vc.x)); ull u0 = pack2(f.x, f.y);
            ffma2(acc1[0], u0, wA0.x); ffma2(acc1[1], u0, wA0.y);
            ffma2(acc1[2], u0, wA1.x); ffma2(acc1[3], u0, wA1.y);
            f = __half22float2(u2h(vc.y)); ull u1 = pack2(f.x, f.y);
            ffma2(acc1[0], u1, wB0.x); ffma2(acc1[1], u1, wB0.y);
            ffma2(acc1[2], u1, wB1.x); ffma2(acc1[3], u1, wB1.y);
        }

        if (e0 + ep < E) {
            int2 ds = dssm[ep];
            float2 u0 = unpack2(acc0[0]), u1 = unpack2(acc0[1]);
            float2 u2 = unpack2(acc0[2]), u3 = unpack2(acc0[3]);
            float4 r = make_float4(u0.x + u0.y + b2s[4 * h],
                                   u1.x + u1.y + b2s[4 * h + 1],
                                   u2.x + u2.y + b2s[4 * h + 2],
                                   u3.x + u3.y + b2s[4 * h + 3]);
            *(float4*)(out + (size_t)ds.x * OUT_COLS + ds.y * 8 + 4 * h) = r;
        }
        if (e0 + ep + 128 < E) {
            int2 ds = dssm[ep + 128];
            float2 u0 = unpack2(acc1[0]), u1 = unpack2(acc1[1]);
            float2 u2 = unpack2(acc1[2]), u3 = unpack2(acc1[3]);
            float4 r = make_float4(u0.x + u0.y + b2s[4 * h],
                                   u1.x + u1.y + b2s[4 * h + 1],
                                   u2.x + u2.y + b2s[4 * h + 2],
                                   u3.x + u3.y + b2s[4 * h + 3]);
            *(float4*)(out + (size_t)ds.x * OUT_COLS + ds.y * 8 + 4 * h) = r;
        }
    } else {
        const int tz = t - 256;          // 0..255
        // ---- zero out[:,128:256) for the block's 16 agents ----------------
        {
            float4 z = make_float4(0.f, 0.f, 0.f, 0.f);
#pragma unroll
            for (int i = tz; i < 512; i += 256) {
                int a = ag0 + (i >> 5);
                if (a < Na)
                    *(float4*)(out + (size_t)a * OUT_COLS + 128 + (i & 31) * 4) = z;
            }
        }
        // ---- own scores: 8 threads per agent ------------------------------
        if (tz < 128) {
            int a  = ag0 + (tz >> 3);
            int jj = tz & 7;
            if (a < Na) {
                const float4* xr4 = (const float4*)(xa + (size_t)a * 128);
                float4 a4[4];
#pragma unroll
                for (int i = 0; i < 4; i++) a4[i] = xr4[jj + 8 * i];

                ull acc[4] = {0ull, 0ull, 0ull, 0ull};
#pragma unroll
                for (int i = 0; i < 4; i++) {
                    const float* wb = was + (jj + 8 * i) * 36;
#pragma unroll
                    for (int q = 0; q < 4; q++) {
                        float v = (q == 0) ? a4[i].x : (q == 1) ? a4[i].y
                                : (q == 2) ? a4[i].z : a4[i].w;
                        ull vv = pack2(v, v);
                        const ull* w = (const ull*)(wb + q * 8);
                        ffma2(acc[0], vv, w[0]);
                        ffma2(acc[1], vv, w[1]);
                        ffma2(acc[2], vv, w[2]);
                        ffma2(acc[3], vv, w[3]);
                    }
                }
#pragma unroll
                for (int d = 1; d < 8; d <<= 1) {
#pragma unroll
                    for (int p = 0; p < 4; p++)
                        acc[p] = add2(acc[p], __shfl_xor_sync(0xffffffffu, acc[p], d));
                }
                float2 u = unpack2(acc[jj >> 1]);
                float s = ((jj & 1) ? u.y : u.x) + bas[jj];
                out[(size_t)a * OUT_COLS + 256 + jj] = s;
            }
        }
    }
}

// ---------------------------------------------------------------------------
extern "C" void kernel_launch(void* const* d_in, const int* in_sizes, int n_in,
                              void* d_out, int out_size)
{
    const float* x_nbr   = (const float*)d_in[0];
    const float* x_agent = (const float*)d_in[1];
    const float* W1      = (const float*)d_in[2];
    const float* b1      = (const float*)d_in[3];
    const float* W2      = (const float*)d_in[4];
    const float* b2      = (const float*)d_in[5];
    const float* Wa      = (const float*)d_in[6];
    const float* ba      = (const float*)d_in[7];
    const void*  esrc    = d_in[8];
    const void*  edst    = d_in[9];
    const void*  eslot   = d_in[10];

    int Nn = in_sizes[0] / HID;
    int Na = in_sizes[1] / HID;
    int E  = in_sizes[8];
    float* out = (float*)d_out;

    const int gemm_smem = 64 * 128 * 8 + 64 * 132 * 4;   // 99328 B
    cudaFuncSetAttribute(gemm_x128, cudaFuncAttributeMaxDynamicSharedMemorySize,
                         gemm_smem);
    const int edge_smem = 256 * 64 * 4;                  // 65536 B dynamic
    cudaFuncSetAttribute(edge_fused_kernel,
                         cudaFuncAttributeMaxDynamicSharedMemorySize, edge_smem);

    int Nmax = Nn > Na ? Nn : Na;
    dim3 ggrid((Nmax + 63) / 64, 2);
    gemm_x128<<<ggrid, 256, gemm_smem>>>(x_nbr, x_agent, W1, b1, Nn, Na);

    int blocks_e = (E + 255) / 256;
    int blocks_a = (Na + 15) / 16;
    int blocks = blocks_e > blocks_a ? blocks_e : blocks_a;
    edge_fused_kernel<<<blocks, 512, edge_smem>>>(W2, b2, Wa, ba, x_agent,
                                                  esrc, edst, eslot, out, E, Na);
}

// round 15
// speedup vs baseline: 1.3713x; 1.2991x over previous
#include <cuda_runtime.h>
#include <cuda_fp16.h>

#define HID 128
#define OUT_COLS 264
#define MAXN 50176

typedef unsigned long long ull;
typedef unsigned int uint;

// fp16 storage of projected node features (half2 packed as uint)
__device__ uint g_Pn[(size_t)MAXN * 64];   // x_nbr  @ W1[:128]
__device__ uint g_Pa[(size_t)MAXN * 64];   // x_agent@ W1[128:] + b1

// ---- packed helpers --------------------------------------------------------
__device__ __forceinline__ ull pack2(float lo, float hi) {
    ull r; asm("mov.b64 %0, {%1,%2};" : "=l"(r) : "f"(lo), "f"(hi)); return r;
}
__device__ __forceinline__ void ffma2(ull& d, ull a, ull b) {
    asm("fma.rn.f32x2 %0, %1, %2, %0;" : "+l"(d) : "l"(a), "l"(b));
}
__device__ __forceinline__ ull add2(ull a, ull b) {
    ull r; asm("add.rn.f32x2 %0, %1, %2;" : "=l"(r) : "l"(a), "l"(b)); return r;
}
__device__ __forceinline__ float2 unpack2(ull v) {
    float2 r; asm("mov.b64 {%0,%1}, %2;" : "=f"(r.x), "=f"(r.y) : "l"(v)); return r;
}
__device__ __forceinline__ uint h2u(__half2 h) { return *reinterpret_cast<uint*>(&h); }
__device__ __forceinline__ __half2 u2h(uint u) { return *reinterpret_cast<__half2*>(&u); }

__device__ __forceinline__ void mma16816(float* d, uint a0, uint a1, uint a2,
                                         uint a3, uint b0, uint b1) {
    asm volatile(
        "mma.sync.aligned.m16n8k16.row.col.f32.f16.f16.f32 "
        "{%0,%1,%2,%3}, {%4,%5,%6,%7}, {%8,%9}, {%0,%1,%2,%3};"
        : "+f"(d[0]), "+f"(d[1]), "+f"(d[2]), "+f"(d[3])
        : "r"(a0), "r"(a1), "r"(a2), "r"(a3), "r"(b0), "r"(b1));
}

// ---------------------------------------------------------------------------
// P[N,128] = fp16(X)[N,128] @ fp16(W)[128,128] (+bias), fp32 accum (HMMA).
// Block 256 thr = 8 warps: 4 over m (m16 each -> m64), 2 over n (n64 each).
// Smem: wsm[n][k] fp16 stride 136, xsm[r][k] fp16 stride 136 (conflict-free:
// bank = 4*(lane>>2) + (lane&3), all distinct).
__global__ __launch_bounds__(256) void gemm_x128(
    const float* __restrict__ X0, const float* __restrict__ X1,
    const float* __restrict__ W1, const float* __restrict__ b1,
    int N0, int N1)
{
    extern __shared__ __half smh[];
    __half* wsm = smh;                    // [128][136]
    __half* xsm = smh + 128 * 136;        // [64][136]
    const int t = threadIdx.x;
    const int sel = blockIdx.y;
    const float* __restrict__ X = sel ? X1 : X0;
    const float* __restrict__ W = sel ? (W1 + 128 * 128) : W1;
    uint* __restrict__ P = sel ? g_Pa : g_Pn;
    const int N = sel ? N1 : N0;
    const int row0 = blockIdx.x * 64;
    if (row0 >= N) return;

    // stage W transposed: wsm[n*136 + k] = fp16(W[k][n])
    for (int i = t; i < 16384; i += 256) {
        int k = i >> 7, n = i & 127;
        wsm[n * 136 + k] = __float2half_rn(W[k * 128 + n]);
    }
    // stage X tile fp16: xsm[r*136 + k]
    for (int i = t; i < 2048; i += 256) {
        int r = i >> 5, c4 = i & 31;
        float4 v = make_float4(0.f, 0.f, 0.f, 0.f);
        int gr = row0 + r;
        if (gr < N) v = ((const float4*)X)[(size_t)gr * 32 + c4];
        *(uint2*)(xsm + r * 136 + c4 * 4) =
            make_uint2(h2u(__floats2half2_rn(v.x, v.y)),
                       h2u(__floats2half2_rn(v.z, v.w)));
    }
    __syncthreads();

    const int lane = t & 31;
    const int wid  = t >> 5;
    const int m0 = (wid & 3) * 16;
    const int n0 = (wid >> 2) * 64;
    const int qr = lane >> 2;     // 0..7
    const int qc = lane & 3;      // 0..3

    float d[8][4];
#pragma unroll
    for (int nt = 0; nt < 8; nt++)
#pragma unroll
        for (int p = 0; p < 4; p++) d[nt][p] = 0.f;

#pragma unroll
    for (int k0 = 0; k0 < 128; k0 += 16) {
        const __half* xr0 = xsm + (m0 + qr) * 136 + k0 + qc * 2;
        const __half* xr1 = xr0 + 8 * 136;
        uint a0 = *(const uint*)xr0;
        uint a1 = *(const uint*)xr1;
        uint a2 = *(const uint*)(xr0 + 8);
        uint a3 = *(const uint*)(xr1 + 8);
#pragma unroll
        for (int nt = 0; nt < 8; nt++) {
            const __half* wr = wsm + (n0 + nt * 8 + qr) * 136 + k0 + qc * 2;
            uint b0  = *(const uint*)wr;
            uint b1v = *(const uint*)(wr + 8);
            mma16816(d[nt], a0, a1, a2, a3, b0, b1v);
        }
    }

#pragma unroll
    for (int nt = 0; nt < 8; nt++) {
        int c0 = n0 + nt * 8 + qc * 2;
        float bvx = 0.f, bvy = 0.f;
        if (sel) { float2 bb = *(const float2*)(b1 + c0); bvx = bb.x; bvy = bb.y; }
        int gr = row0 + m0 + qr;
        if (gr < N)
            P[(size_t)gr * 64 + (c0 >> 1)] =
                h2u(__floats2half2_rn(d[nt][0] + bvx, d[nt][1] + bvy));
        if (gr + 8 < N)
            P[(size_t)(gr + 8) * 64 + (c0 >> 1)] =
                h2u(__floats2half2_rn(d[nt][2] + bvx, d[nt][3] + bvy));
    }
}

// ---------------------------------------------------------------------------
// Two-phase fused edge kernel (R14, unchanged). Block = 512 thr, 256 edges.
__global__ __launch_bounds__(512, 2) void edge_fused_kernel(
    const float* __restrict__ W2, const float* __restrict__ b2,
    const float* __restrict__ Wa, const float* __restrict__ ba,
    const float* __restrict__ xa,
    const void* __restrict__ esrc, const void* __restrict__ edst,
    const void* __restrict__ eslot,
    float* __restrict__ out, int E, int Na)
{
    extern __shared__ uint v_sm[];       // [256][64] uints = 64 KB dynamic
    __shared__ ull   w2p[64 * 8];
    __shared__ float was[32 * 36];
    __shared__ int2  dssm[256];
    __shared__ float b2s[8], bas[8];

    const int t = threadIdx.x;

    for (int i = t; i < 512; i += 512) {
        int kp = i >> 3, c = i & 7;
        w2p[i] = pack2(W2[(2 * kp) * 8 + c], W2[(2 * kp + 1) * 8 + c]);
    }
    for (int i = t; i < 1024; i += 512) {
        int k = i >> 3, c = i & 7;
        was[(k >> 2) * 36 + (k & 3) * 8 + c] = Wa[i];
    }
    if (t < 8) { b2s[t] = b2[t]; bas[t] = ba[t]; }

    const int idx64 = (((const int*)eslot)[1] != 1);
    const int e0 = blockIdx.x * 256;
    const int ag0 = blockIdx.x * 16;
    const __half2 z2 = __floats2half2_rn(0.f, 0.f);

    // ---- phase 1: gather + relu -> v_sm, stage dst/slot (all 512) ---------
    {
        const int j  = t & 7;
        const int eb = t >> 3;
#pragma unroll
        for (int s = 0; s < 4; s++) {
            int el = eb + 64 * s;
            int eg = e0 + el;
            if (eg < E) {
                int src, dst, slot;
                if (idx64) { src  = ((const int*)esrc)[2 * eg];
                             dst  = ((const int*)edst)[2 * eg];
                             slot = ((const int*)eslot)[2 * eg]; }
                else       { src  = ((const int*)esrc)[eg];
                             dst  = ((const int*)edst)[eg];
                             slot = ((const int*)eslot)[eg]; }
                if (j == 0) dssm[el] = make_int2(dst, slot);

                const uint4* pr = (const uint4*)(g_Pn + (size_t)src * 64);
                const uint4* ar = (const uint4*)(g_Pa + (size_t)dst * 64);
                uint4 A0 = pr[j], A1 = pr[j + 8];
                uint4 C0 = ar[j], C1 = ar[j + 8];
                uint4 V0, V1;
                V0.x = h2u(__hmax2(__hadd2(u2h(A0.x), u2h(C0.x)), z2));
                V0.y = h2u(__hmax2(__hadd2(u2h(A0.y), u2h(C0.y)), z2));
                V0.z = h2u(__hmax2(__hadd2(u2h(A0.z), u2h(C0.z)), z2));
                V0.w = h2u(__hmax2(__hadd2(u2h(A0.w), u2h(C0.w)), z2));
                V1.x = h2u(__hmax2(__hadd2(u2h(A1.x), u2h(C1.x)), z2));
                V1.y = h2u(__hmax2(__hadd2(u2h(A1.y), u2h(C1.y)), z2));
                V1.z = h2u(__hmax2(__hadd2(u2h(A1.z), u2h(C1.z)), z2));
                V1.w = h2u(__hmax2(__hadd2(u2h(A1.w), u2h(C1.w)), z2));

                const int xr = 2 * (el & 15);
                uint* vb = v_sm + el * 64;
                int q0 = (4 * j) ^ xr;
                *(uint2*)(vb + q0)       = make_uint2(V0.x, V0.y);
                *(uint2*)(vb + (q0 ^ 2)) = make_uint2(V0.z, V0.w);
                int q1 = q0 + 32;
                *(uint2*)(vb + q1)       = make_uint2(V1.x, V1.y);
                *(uint2*)(vb + (q1 ^ 2)) = make_uint2(V1.z, V1.w);
            }
        }
    }
    __syncthreads();

    if (t < 256) {
        const int ep = t >> 1;
        const int h  = t & 1;
        const int xr = 2 * (ep & 15);
        const uint* vb0 = v_sm + ep * 64;
        const uint* vb1 = v_sm + (ep + 128) * 64;

        ull acc0[4] = {0ull, 0ull, 0ull, 0ull};
        ull acc1[4] = {0ull, 0ull, 0ull, 0ull};

#pragma unroll 8
        for (int kp = 0; kp < 64; kp += 2) {
            const ull* wa_ = w2p + kp * 8 + 4 * h;
            const ull* wb_ = w2p + (kp + 1) * 8 + 4 * h;
            ulonglong2 wA0 = *(const ulonglong2*)wa_;
            ulonglong2 wA1 = *(const ulonglong2*)(wa_ + 2);
            ulonglong2 wB0 = *(const ulonglong2*)wb_;
            ulonglong2 wB1 = *(const ulonglong2*)(wb_ + 2);
            uint2 va = *(const uint2*)(vb0 + (kp ^ xr));
            uint2 vc = *(const uint2*)(vb1 + (kp ^ xr));

            float2 f;
            f = __half22float2(u2h(va.x)); ull v0 = pack2(f.x, f.y);
            ffma2(acc0[0], v0, wA0.x); ffma2(acc0[1], v0, wA0.y);
            ffma2(acc0[2], v0, wA1.x); ffma2(acc0[3], v0, wA1.y);
            f = __half22float2(u2h(va.y)); ull v1 = pack2(f.x, f.y);
            ffma2(acc0[0], v1, wB0.x); ffma2(acc0[1], v1, wB0.y);
            ffma2(acc0[2], v1, wB1.x); ffma2(acc0[3], v1, wB1.y);

            f = __half22float2(u2h(vc.x)); ull u0 = pack2(f.x, f.y);
            ffma2(acc1[0], u0, wA0.x); ffma2(acc1[1], u0, wA0.y);
            ffma2(acc1[2], u0, wA1.x); ffma2(acc1[3], u0, wA1.y);
            f = __half22float2(u2h(vc.y)); ull u1 = pack2(f.x, f.y);
            ffma2(acc1[0], u1, wB0.x); ffma2(acc1[1], u1, wB0.y);
            ffma2(acc1[2], u1, wB1.x); ffma2(acc1[3], u1, wB1.y);
        }

        if (e0 + ep < E) {
            int2 ds = dssm[ep];
            float2 u0 = unpack2(acc0[0]), u1 = unpack2(acc0[1]);
            float2 u2 = unpack2(acc0[2]), u3 = unpack2(acc0[3]);
            float4 r = make_float4(u0.x + u0.y + b2s[4 * h],
                                   u1.x + u1.y + b2s[4 * h + 1],
                                   u2.x + u2.y + b2s[4 * h + 2],
                                   u3.x + u3.y + b2s[4 * h + 3]);
            *(float4*)(out + (size_t)ds.x * OUT_COLS + ds.y * 8 + 4 * h) = r;
        }
        if (e0 + ep + 128 < E) {
            int2 ds = dssm[ep + 128];
            float2 u0 = unpack2(acc1[0]), u1 = unpack2(acc1[1]);
            float2 u2 = unpack2(acc1[2]), u3 = unpack2(acc1[3]);
            float4 r = make_float4(u0.x + u0.y + b2s[4 * h],
                                   u1.x + u1.y + b2s[4 * h + 1],
                                   u2.x + u2.y + b2s[4 * h + 2],
                                   u3.x + u3.y + b2s[4 * h + 3]);
            *(float4*)(out + (size_t)ds.x * OUT_COLS + ds.y * 8 + 4 * h) = r;
        }
    } else {
        const int tz = t - 256;
        {
            float4 z = make_float4(0.f, 0.f, 0.f, 0.f);
#pragma unroll
            for (int i = tz; i < 512; i += 256) {
                int a = ag0 + (i >> 5);
                if (a < Na)
                    *(float4*)(out + (size_t)a * OUT_COLS + 128 + (i & 31) * 4) = z;
            }
        }
        if (tz < 128) {
            int a  = ag0 + (tz >> 3);
            int jj = tz & 7;
            if (a < Na) {
                const float4* xr4 = (const float4*)(xa + (size_t)a * 128);
                float4 a4[4];
#pragma unroll
                for (int i = 0; i < 4; i++) a4[i] = xr4[jj + 8 * i];

                ull acc[4] = {0ull, 0ull, 0ull, 0ull};
#pragma unroll
                for (int i = 0; i < 4; i++) {
                    const float* wb = was + (jj + 8 * i) * 36;
#pragma unroll
                    for (int q = 0; q < 4; q++) {
                        float v = (q == 0) ? a4[i].x : (q == 1) ? a4[i].y
                                : (q == 2) ? a4[i].z : a4[i].w;
                        ull vv = pack2(v, v);
                        const ull* w = (const ull*)(wb + q * 8);
                        ffma2(acc[0], vv, w[0]);
                        ffma2(acc[1], vv, w[1]);
                        ffma2(acc[2], vv, w[2]);
                        ffma2(acc[3], vv, w[3]);
                    }
                }
#pragma unroll
                for (int d = 1; d < 8; d <<= 1) {
#pragma unroll
                    for (int p = 0; p < 4; p++)
                        acc[p] = add2(acc[p], __shfl_xor_sync(0xffffffffu, acc[p], d));
                }
                float2 u = unpack2(acc[jj >> 1]);
                float s = ((jj & 1) ? u.y : u.x) + bas[jj];
                out[(size_t)a * OUT_COLS + 256 + jj] = s;
            }
        }
    }
}

// ---------------------------------------------------------------------------
extern "C" void kernel_launch(void* const* d_in, const int* in_sizes, int n_in,
                              void* d_out, int out_size)
{
    const float* x_nbr   = (const float*)d_in[0];
    const float* x_agent = (const float*)d_in[1];
    const float* W1      = (const float*)d_in[2];
    const float* b1      = (const float*)d_in[3];
    const float* W2      = (const float*)d_in[4];
    const float* b2      = (const float*)d_in[5];
    const float* Wa      = (const float*)d_in[6];
    const float* ba      = (const float*)d_in[7];
    const void*  esrc    = d_in[8];
    const void*  edst    = d_in[9];
    const void*  eslot   = d_in[10];

    int Nn = in_sizes[0] / HID;
    int Na = in_sizes[1] / HID;
    int E  = in_sizes[8];
    float* out = (float*)d_out;

    const int gemm_smem = (128 + 64) * 136 * 2;          // 52224 B
    cudaFuncSetAttribute(gemm_x128, cudaFuncAttributeMaxDynamicSharedMemorySize,
                         gemm_smem);
    const int edge_smem = 256 * 64 * 4;                  // 65536 B dynamic
    cudaFuncSetAttribute(edge_fused_kernel,
                         cudaFuncAttributeMaxDynamicSharedMemorySize, edge_smem);

    int Nmax = Nn > Na ? Nn : Na;
    dim3 ggrid((Nmax + 63) / 64, 2);
    gemm_x128<<<ggrid, 256, gemm_smem>>>(x_nbr, x_agent, W1, b1, Nn, Na);

    int blocks_e = (E + 255) / 256;
    int blocks_a = (Na + 15) / 16;
    int blocks = blocks_e > blocks_a ? blocks_e : blocks_a;
    edge_fused_kernel<<<blocks, 512, edge_smem>>>(W2, b2, Wa, ba, x_agent,
                                                  esrc, edst, eslot, out, E, Na);
}

// round 16
// speedup vs baseline: 1.6146x; 1.1774x over previous
#include <cuda_runtime.h>
#include <cuda_fp16.h>

#define HID 128
#define OUT_COLS 264
#define MAXN 50176

typedef unsigned long long ull;
typedef unsigned int uint;

// fp16 storage of projected node features (half2 packed as uint)
__device__ uint g_Pn[(size_t)MAXN * 64];     // x_nbr  @ W1[:128]
__device__ uint g_Pa[(size_t)MAXN * 64];     // x_agent@ W1[128:] + b1
__device__ __half g_W1h[2 * 128 * 128];      // fp16 W1, transposed [sel][n][k]
__device__ __half g_W2h[8 * 128];            // fp16 W2, transposed [n][k]

// ---- helpers ---------------------------------------------------------------
__device__ __forceinline__ ull pack2(float lo, float hi) {
    ull r; asm("mov.b64 %0, {%1,%2};" : "=l"(r) : "f"(lo), "f"(hi)); return r;
}
__device__ __forceinline__ void ffma2(ull& d, ull a, ull b) {
    asm("fma.rn.f32x2 %0, %1, %2, %0;" : "+l"(d) : "l"(a), "l"(b));
}
__device__ __forceinline__ ull add2(ull a, ull b) {
    ull r; asm("add.rn.f32x2 %0, %1, %2;" : "=l"(r) : "l"(a), "l"(b)); return r;
}
__device__ __forceinline__ float2 unpack2(ull v) {
    float2 r; asm("mov.b64 {%0,%1}, %2;" : "=f"(r.x), "=f"(r.y) : "l"(v)); return r;
}
__device__ __forceinline__ uint h2u(__half2 h) { return *reinterpret_cast<uint*>(&h); }
__device__ __forceinline__ __half2 u2h(uint u) { return *reinterpret_cast<__half2*>(&u); }

__device__ __forceinline__ void mma16816(float* d, uint a0, uint a1, uint a2,
                                         uint a3, uint b0, uint b1) {
    asm volatile(
        "mma.sync.aligned.m16n8k16.row.col.f32.f16.f16.f32 "
        "{%0,%1,%2,%3}, {%4,%5,%6,%7}, {%8,%9}, {%0,%1,%2,%3};"
        : "+f"(d[0]), "+f"(d[1]), "+f"(d[2]), "+f"(d[3])
        : "r"(a0), "r"(a1), "r"(a2), "r"(a3), "r"(b0), "r"(b1));
}

// ---------------------------------------------------------------------------
// One-time weight conversion: W1 -> fp16 transposed [sel][n][k]; W2 -> [n][k].
__global__ void convert_weights(const float* __restrict__ W1,
                                const float* __restrict__ W2) {
    int i = blockIdx.x * 256 + threadIdx.x;     // grid 128 -> 32768 threads
    {   // W1: 2 x 128k x 128n
        int sel = i >> 14, r = i & 16383, k = r >> 7, n = r & 127;
        g_W1h[sel * 16384 + n * 128 + k] =
            __float2half_rn(W1[sel * 16384 + k * 128 + n]);
    }
    if (i < 1024) {                             // W2: 128k x 8n
        int k = i >> 3, n = i & 7;
        g_W2h[n * 128 + k] = __float2half_rn(W2[k * 8 + n]);
    }
}

// ---------------------------------------------------------------------------
// P[N,128] = fp16(X) @ fp16(W) (+bias), fp32 accum (HMMA). W pre-converted.
__global__ __launch_bounds__(256, 3) void gemm_x128(
    const float* __restrict__ X0, const float* __restrict__ X1,
    const float* __restrict__ b1, int N0, int N1)
{
    extern __shared__ __half smh[];
    __half* wsm = smh;                    // [128 n][136 k]
    __half* xsm = smh + 128 * 136;        // [64 r][136 k]
    const int t = threadIdx.x;
    const int sel = blockIdx.y;
    const float* __restrict__ X = sel ? X1 : X0;
    uint* __restrict__ P = sel ? g_Pa : g_Pn;
    const int N = sel ? N1 : N0;
    const int row0 = blockIdx.x * 64;
    if (row0 >= N) return;

    // stage pre-converted W slice: 8 x (LDG.128 + STS.128) per thread
    {
        const __half* Wh = g_W1h + sel * 16384;
        for (int i = t; i < 2048; i += 256) {
            int n = i >> 4, v = i & 15;
            *(uint4*)(wsm + n * 136 + v * 8) = ((const uint4*)(Wh + n * 128))[v];
        }
    }
    // stage X tile fp16
    for (int i = t; i < 2048; i += 256) {
        int r = i >> 5, c4 = i & 31;
        float4 v = make_float4(0.f, 0.f, 0.f, 0.f);
        int gr = row0 + r;
        if (gr < N) v = ((const float4*)X)[(size_t)gr * 32 + c4];
        *(uint2*)(xsm + r * 136 + c4 * 4) =
            make_uint2(h2u(__floats2half2_rn(v.x, v.y)),
                       h2u(__floats2half2_rn(v.z, v.w)));
    }
    __syncthreads();

    const int lane = t & 31;
    const int wid  = t >> 5;
    const int m0 = (wid & 3) * 16;
    const int n0 = (wid >> 2) * 64;
    const int qr = lane >> 2;
    const int qc = lane & 3;

    float d[8][4];
#pragma unroll
    for (int nt = 0; nt < 8; nt++)
#pragma unroll
        for (int p = 0; p < 4; p++) d[nt][p] = 0.f;

#pragma unroll
    for (int k0 = 0; k0 < 128; k0 += 16) {
        const __half* xr0 = xsm + (m0 + qr) * 136 + k0 + qc * 2;
        const __half* xr1 = xr0 + 8 * 136;
        uint a0 = *(const uint*)xr0;
        uint a1 = *(const uint*)xr1;
        uint a2 = *(const uint*)(xr0 + 8);
        uint a3 = *(const uint*)(xr1 + 8);
#pragma unroll
        for (int nt = 0; nt < 8; nt++) {
            const __half* wr = wsm + (n0 + nt * 8 + qr) * 136 + k0 + qc * 2;
            uint b0  = *(const uint*)wr;
            uint b1v = *(const uint*)(wr + 8);
            mma16816(d[nt], a0, a1, a2, a3, b0, b1v);
        }
    }

#pragma unroll
    for (int nt = 0; nt < 8; nt++) {
        int c0 = n0 + nt * 8 + qc * 2;
        float bvx = 0.f, bvy = 0.f;
        if (sel) { float2 bb = *(const float2*)(b1 + c0); bvx = bb.x; bvy = bb.y; }
        int gr = row0 + m0 + qr;
        if (gr < N)
            P[(size_t)gr * 64 + (c0 >> 1)] =
                h2u(__floats2half2_rn(d[nt][0] + bvx, d[nt][1] + bvy));
        if (gr + 8 < N)
            P[(size_t)(gr + 8) * 64 + (c0 >> 1)] =
                h2u(__floats2half2_rn(d[nt][2] + bvx, d[nt][3] + bvy));
    }
}

// ---------------------------------------------------------------------------
// Edge kernel v5. Block = 512 threads, 192 edges = 12 agents, 3 blocks/SM.
// Phase 1 (all): gather+relu -> v_sm [192][64] uints, XOR swizzle 2*(el&15);
//                stage (dst,slot).
// Phase 2: warps 0-11: HMMA m16n8k16 — warp w = edges [16w,16w+16), A-frags
//          from v_sm (swizzle-aware), B-frags (fp16 W2) in regs from g_W2h,
//          fp32 accum, scatter float2 stores.
//          warps 12-15: zero out[:,128:256) + own-score for the 12 agents.
__global__ __launch_bounds__(512, 3) void edge_fused_kernel(
    const float* __restrict__ b2,
    const float* __restrict__ Wa, const float* __restrict__ ba,
    const float* __restrict__ xa,
    const void* __restrict__ esrc, const void* __restrict__ edst,
    const void* __restrict__ eslot,
    float* __restrict__ out, int E, int Na)
{
    extern __shared__ uint v_sm[];       // [192][64] = 48 KB dynamic
    __shared__ float was[32 * 36];       // own-score weights, stride-36 layout
    __shared__ int2  dssm[192];
    __shared__ float bas[8];

    const int t = threadIdx.x;

    for (int i = t; i < 1024; i += 512) {
        int k = i >> 3, c = i & 7;
        was[(k >> 2) * 36 + (k & 3) * 8 + c] = Wa[i];
    }
    if (t < 8) bas[t] = ba[t];

    const int idx64 = (((const int*)eslot)[1] != 1);
    const int e0 = blockIdx.x * 192;
    const int ag0 = blockIdx.x * 12;
    const __half2 z2 = __floats2half2_rn(0.f, 0.f);

    // ---- phase 1: gather + relu -> v_sm, stage dst/slot -------------------
    {
        const int j  = t & 7;
        const int eb = t >> 3;           // 0..63
#pragma unroll
        for (int s = 0; s < 3; s++) {
            int el = eb + 64 * s;        // 0..191
            int eg = e0 + el;
            if (eg < E) {
                int src, dst, slot;
                if (idx64) { src  = ((const int*)esrc)[2 * eg];
                             dst  = ((const int*)edst)[2 * eg];
                             slot = ((const int*)eslot)[2 * eg]; }
                else       { src  = ((const int*)esrc)[eg];
                             dst  = ((const int*)edst)[eg];
                             slot = ((const int*)eslot)[eg]; }
                if (j == 0) dssm[el] = make_int2(dst, slot);

                const uint4* pr = (const uint4*)(g_Pn + (size_t)src * 64);
                const uint4* ar = (const uint4*)(g_Pa + (size_t)dst * 64);
                uint4 A0 = pr[j], A1 = pr[j + 8];
                uint4 C0 = ar[j], C1 = ar[j + 8];
                uint4 V0, V1;
                V0.x = h2u(__hmax2(__hadd2(u2h(A0.x), u2h(C0.x)), z2));
                V0.y = h2u(__hmax2(__hadd2(u2h(A0.y), u2h(C0.y)), z2));
                V0.z = h2u(__hmax2(__hadd2(u2h(A0.z), u2h(C0.z)), z2));
                V0.w = h2u(__hmax2(__hadd2(u2h(A0.w), u2h(C0.w)), z2));
                V1.x = h2u(__hmax2(__hadd2(u2h(A1.x), u2h(C1.x)), z2));
                V1.y = h2u(__hmax2(__hadd2(u2h(A1.y), u2h(C1.y)), z2));
                V1.z = h2u(__hmax2(__hadd2(u2h(A1.z), u2h(C1.z)), z2));
                V1.w = h2u(__hmax2(__hadd2(u2h(A1.w), u2h(C1.w)), z2));

                const int xr = 2 * (el & 15);
                uint* vb = v_sm + el * 64;
                int q0 = (4 * j) ^ xr;
                *(uint2*)(vb + q0)       = make_uint2(V0.x, V0.y);
                *(uint2*)(vb + (q0 ^ 2)) = make_uint2(V0.z, V0.w);
                int q1 = q0 + 32;
                *(uint2*)(vb + q1)       = make_uint2(V1.x, V1.y);
                *(uint2*)(vb + (q1 ^ 2)) = make_uint2(V1.z, V1.w);
            }
        }
    }
    __syncthreads();

    const int wid  = t >> 5;
    const int lane = t & 31;

    if (wid < 12) {
        // ---- phase 2: HMMA, 16 edges per warp -----------------------------
        const int qr = lane >> 2;        // 0..7
        const int qc = lane & 3;         // 0..3
        const int m0 = wid * 16;

        // B-fragments from pre-converted g_W2h (L1-resident, 4KB table)
        uint bf0[8], bf1[8];
        const __half* wb = g_W2h + qr * 128 + 2 * qc;
#pragma unroll
        for (int s = 0; s < 8; s++) {
            bf0[s] = *(const uint*)(wb + 16 * s);
            bf1[s] = *(const uint*)(wb + 16 * s + 8);
        }

        const uint* row0 = v_sm + (m0 + qr) * 64;
        const uint* row1 = v_sm + (m0 + 8 + qr) * 64;
        const int x0 = 2 * qr;           // (m0+qr)&15 = qr
        const int x1 = 2 * qr + 16;      // (m0+8+qr)&15 = qr+8

        float d[4] = {0.f, 0.f, 0.f, 0.f};
#pragma unroll
        for (int s = 0; s < 8; s++) {
            int kq = s * 8 + qc;
            uint a0 = row0[kq ^ x0];
            uint a1 = row1[kq ^ x1];
            uint a2 = row0[(kq + 4) ^ x0];
            uint a3 = row1[(kq + 4) ^ x1];
            mma16816(d, a0, a1, a2, a3, bf0[s], bf1[s]);
        }

        float2 bb = *(const float2*)(b2 + 2 * qc);
        if (e0 + m0 + qr < E) {
            int2 ds = dssm[m0 + qr];
            *(float2*)(out + (size_t)ds.x * OUT_COLS + ds.y * 8 + 2 * qc) =
                make_float2(d[0] + bb.x, d[1] + bb.y);
        }
        if (e0 + m0 + 8 + qr < E) {
            int2 ds = dssm[m0 + 8 + qr];
            *(float2*)(out + (size_t)ds.x * OUT_COLS + ds.y * 8 + 2 * qc) =
                make_float2(d[2] + bb.x, d[3] + bb.y);
        }
    } else {
        const int tz = t - 384;          // 0..127
        // ---- zero out[:,128:256) for the block's 12 agents ----------------
        {
            float4 z = make_float4(0.f, 0.f, 0.f, 0.f);
#pragma unroll
            for (int i = tz; i < 384; i += 128) {   // 12 agents x 32 float4
                int a = ag0 + (i >> 5);
                if (a < Na)
                    *(float4*)(out + (size_t)a * OUT_COLS + 128 + (i & 31) * 4) = z;
            }
        }
        // ---- own scores: 8 threads per agent (12 agents = 96 threads) -----
        if (tz < 96) {
            int a  = ag0 + (tz >> 3);
            int jj = tz & 7;
            if (a < Na) {
                const float4* xr4 = (const float4*)(xa + (size_t)a * 128);
                float4 a4[4];
#pragma unroll
                for (int i = 0; i < 4; i++) a4[i] = xr4[jj + 8 * i];

                ull acc[4] = {0ull, 0ull, 0ull, 0ull};
#pragma unroll
                for (int i = 0; i < 4; i++) {
                    const float* wbp = was + (jj + 8 * i) * 36;
#pragma unroll
                    for (int q = 0; q < 4; q++) {
                        float v = (q == 0) ? a4[i].x : (q == 1) ? a4[i].y
                                : (q == 2) ? a4[i].z : a4[i].w;
                        ull vv = pack2(v, v);
                        const ull* w = (const ull*)(wbp + q * 8);
                        ffma2(acc[0], vv, w[0]);
                        ffma2(acc[1], vv, w[1]);
                        ffma2(acc[2], vv, w[2]);
                        ffma2(acc[3], vv, w[3]);
                    }
                }
#pragma unroll
                for (int dd = 1; dd < 8; dd <<= 1) {
#pragma unroll
                    for (int p = 0; p < 4; p++)
                        acc[p] = add2(acc[p], __shfl_xor_sync(0xffffffffu, acc[p], dd));
                }
                float2 u = unpack2(acc[jj >> 1]);
                float s = ((jj & 1) ? u.y : u.x) + bas[jj];
                out[(size_t)a * OUT_COLS + 256 + jj] = s;
            }
        }
    }
}

// ---------------------------------------------------------------------------
extern "C" void kernel_launch(void* const* d_in, const int* in_sizes, int n_in,
                              void* d_out, int out_size)
{
    const float* x_nbr   = (const float*)d_in[0];
    const float* x_agent = (const float*)d_in[1];
    const float* W1      = (const float*)d_in[2];
    const float* b1      = (const float*)d_in[3];
    const float* W2      = (const float*)d_in[4];
    const float* b2      = (const float*)d_in[5];
    const float* Wa      = (const float*)d_in[6];
    const float* ba      = (const float*)d_in[7];
    const void*  esrc    = d_in[8];
    const void*  edst    = d_in[9];
    const void*  eslot   = d_in[10];

    int Nn = in_sizes[0] / HID;
    int Na = in_sizes[1] / HID;
    int E  = in_sizes[8];
    float* out = (float*)d_out;

    const int gemm_smem = (128 + 64) * 136 * 2;          // 52224 B
    cudaFuncSetAttribute(gemm_x128, cudaFuncAttributeMaxDynamicSharedMemorySize,
                         gemm_smem);
    const int edge_smem = 192 * 64 * 4;                  // 49152 B dynamic
    cudaFuncSetAttribute(edge_fused_kernel,
                         cudaFuncAttributeMaxDynamicSharedMemorySize, edge_smem);

    convert_weights<<<128, 256>>>(W1, W2);

    int Nmax = Nn > Na ? Nn : Na;
    dim3 ggrid((Nmax + 63) / 64, 2);
    gemm_x128<<<ggrid, 256, gemm_smem>>>(x_nbr, x_agent, b1, Nn, Na);

    int blocks_e = (E + 191) / 192;
    int blocks_a = (Na + 11) / 12;
    int blocks = blocks_e > blocks_a ? blocks_e : blocks_a;
    edge_fused_kernel<<<blocks, 512, edge_smem>>>(b2, Wa, ba, x_agent,
                                                  esrc, edst, eslot, out, E, Na);
}

// round 17
// speedup vs baseline: 1.8147x; 1.1239x over previous
#include <cuda_runtime.h>
#include <cuda_fp16.h>

#define HID 128
#define OUT_COLS 264
#define MAXN 50176

typedef unsigned long long ull;
typedef unsigned int uint;

// fp16 storage of projected node features (half2 packed as uint)
__device__ uint g_Pn[(size_t)MAXN * 64];     // x_nbr  @ W1[:128]
__device__ uint g_Pa[(size_t)MAXN * 64];     // x_agent@ W1[128:] + b1
__device__ __half g_W1h[2 * 128 * 128];      // fp16 W1, transposed [sel][n][k]
__device__ __half g_W2h[8 * 128];            // fp16 W2, transposed [n][k]

// ---- helpers ---------------------------------------------------------------
__device__ __forceinline__ ull pack2(float lo, float hi) {
    ull r; asm("mov.b64 %0, {%1,%2};" : "=l"(r) : "f"(lo), "f"(hi)); return r;
}
__device__ __forceinline__ void ffma2(ull& d, ull a, ull b) {
    asm("fma.rn.f32x2 %0, %1, %2, %0;" : "+l"(d) : "l"(a), "l"(b));
}
__device__ __forceinline__ ull add2(ull a, ull b) {
    ull r; asm("add.rn.f32x2 %0, %1, %2;" : "=l"(r) : "l"(a), "l"(b)); return r;
}
__device__ __forceinline__ float2 unpack2(ull v) {
    float2 r; asm("mov.b64 {%0,%1}, %2;" : "=f"(r.x), "=f"(r.y) : "l"(v)); return r;
}
__device__ __forceinline__ uint h2u(__half2 h) { return *reinterpret_cast<uint*>(&h); }
__device__ __forceinline__ __half2 u2h(uint u) { return *reinterpret_cast<__half2*>(&u); }

__device__ __forceinline__ uint smem_u32(const void* p) {
    uint a;
    asm("{ .reg .u64 tmp; cvta.to.shared.u64 tmp, %1; cvt.u32.u64 %0, tmp; }"
        : "=r"(a) : "l"(p));
    return a;
}

__device__ __forceinline__ void mma16816(float* d, uint a0, uint a1, uint a2,
                                         uint a3, uint b0, uint b1) {
    asm volatile(
        "mma.sync.aligned.m16n8k16.row.col.f32.f16.f16.f32 "
        "{%0,%1,%2,%3}, {%4,%5,%6,%7}, {%8,%9}, {%0,%1,%2,%3};"
        : "+f"(d[0]), "+f"(d[1]), "+f"(d[2]), "+f"(d[3])
        : "r"(a0), "r"(a1), "r"(a2), "r"(a3), "r"(b0), "r"(b1));
}

__device__ __forceinline__ void bulk_cp(uint dst_smem, const void* src,
                                        uint bytes, uint mbar) {
    asm volatile(
        "cp.async.bulk.shared::cta.global.mbarrier::complete_tx::bytes "
        "[%0], [%1], %2, [%3];"
        :: "r"(dst_smem), "l"(src), "r"(bytes), "r"(mbar) : "memory");
}

// ---------------------------------------------------------------------------
// One-time weight conversion: W1 -> fp16 transposed [sel][n][k]; W2 -> [n][k].
__global__ void convert_weights(const float* __restrict__ W1,
                                const float* __restrict__ W2) {
    int i = blockIdx.x * 256 + threadIdx.x;     // grid 128 -> 32768 threads
    {
        int sel = i >> 14, r = i & 16383, k = r >> 7, n = r & 127;
        g_W1h[sel * 16384 + n * 128 + k] =
            __float2half_rn(W1[sel * 16384 + k * 128 + n]);
    }
    if (i < 1024) {
        int k = i >> 3, n = i & 7;
        g_W2h[n * 128 + k] = __float2half_rn(W2[k * 8 + n]);
    }
}

// ---------------------------------------------------------------------------
// P[N,128] = fp16(X) @ fp16(W) (+bias), fp32 accum (HMMA). (R16, unchanged)
__global__ __launch_bounds__(256, 3) void gemm_x128(
    const float* __restrict__ X0, const float* __restrict__ X1,
    const float* __restrict__ b1, int N0, int N1)
{
    extern __shared__ __half smh[];
    __half* wsm = smh;                    // [128 n][136 k]
    __half* xsm = smh + 128 * 136;        // [64 r][136 k]
    const int t = threadIdx.x;
    const int sel = blockIdx.y;
    const float* __restrict__ X = sel ? X1 : X0;
    uint* __restrict__ P = sel ? g_Pa : g_Pn;
    const int N = sel ? N1 : N0;
    const int row0 = blockIdx.x * 64;
    if (row0 >= N) return;

    {
        const __half* Wh = g_W1h + sel * 16384;
        for (int i = t; i < 2048; i += 256) {
            int n = i >> 4, v = i & 15;
            *(uint4*)(wsm + n * 136 + v * 8) = ((const uint4*)(Wh + n * 128))[v];
        }
    }
    for (int i = t; i < 2048; i += 256) {
        int r = i >> 5, c4 = i & 31;
        float4 v = make_float4(0.f, 0.f, 0.f, 0.f);
        int gr = row0 + r;
        if (gr < N) v = ((const float4*)X)[(size_t)gr * 32 + c4];
        *(uint2*)(xsm + r * 136 + c4 * 4) =
            make_uint2(h2u(__floats2half2_rn(v.x, v.y)),
                       h2u(__floats2half2_rn(v.z, v.w)));
    }
    __syncthreads();

    const int lane = t & 31;
    const int wid  = t >> 5;
    const int m0 = (wid & 3) * 16;
    const int n0 = (wid >> 2) * 64;
    const int qr = lane >> 2;
    const int qc = lane & 3;

    float d[8][4];
#pragma unroll
    for (int nt = 0; nt < 8; nt++)
#pragma unroll
        for (int p = 0; p < 4; p++) d[nt][p] = 0.f;

#pragma unroll
    for (int k0 = 0; k0 < 128; k0 += 16) {
        const __half* xr0 = xsm + (m0 + qr) * 136 + k0 + qc * 2;
        const __half* xr1 = xr0 + 8 * 136;
        uint a0 = *(const uint*)xr0;
        uint a1 = *(const uint*)xr1;
        uint a2 = *(const uint*)(xr0 + 8);
        uint a3 = *(const uint*)(xr1 + 8);
#pragma unroll
        for (int nt = 0; nt < 8; nt++) {
            const __half* wr = wsm + (n0 + nt * 8 + qr) * 136 + k0 + qc * 2;
            uint b0  = *(const uint*)wr;
            uint b1v = *(const uint*)(wr + 8);
            mma16816(d[nt], a0, a1, a2, a3, b0, b1v);
        }
    }

#pragma unroll
    for (int nt = 0; nt < 8; nt++) {
        int c0 = n0 + nt * 8 + qc * 2;
        float bvx = 0.f, bvy = 0.f;
        if (sel) { float2 bb = *(const float2*)(b1 + c0); bvx = bb.x; bvy = bb.y; }
        int gr = row0 + m0 + qr;
        if (gr < N)
            P[(size_t)gr * 64 + (c0 >> 1)] =
                h2u(__floats2half2_rn(d[nt][0] + bvx, d[nt][1] + bvy));
        if (gr + 8 < N)
            P[(size_t)(gr + 8) * 64 + (c0 >> 1)] =
                h2u(__floats2half2_rn(d[nt][2] + bvx, d[nt][3] + bvy));
    }
}

// ---------------------------------------------------------------------------
// Edge kernel v6: TMA-gather. Block = 512 thr, 192 edges = 12 agents, 3/SM.
// Phase 1: threads 0..191 each issue ONE cp.async.bulk 256B row copy
//   g_Pn[src] -> pn_sm[el] (rows padded to 68 uints); el%16==0 threads also
//   copy g_Pa[dst] -> pa_sm[el>>4] (one per 16-edge group; edge_dst groups
//   are slot-contiguous per agent). Single mbarrier counts all bytes.
// Phase 2: warps 0-11 wait on the mbarrier, build relu(Pn+Pa) A-fragments
//   on the fly (bank = 4*qr+qc, conflict-free), HMMA m16n8k16, scatter store.
//   Warps 12-15 skip the wait: zero out[:,128:256) + own-score concurrently.
__global__ __launch_bounds__(512, 3) void edge_fused_kernel(
    const float* __restrict__ b2,
    const float* __restrict__ Wa, const float* __restrict__ ba,
    const float* __restrict__ xa,
    const void* __restrict__ esrc, const void* __restrict__ edst,
    const void* __restrict__ eslot,
    float* __restrict__ out, int E, int Na)
{
    extern __shared__ uint dyn_sm[];
    uint* pn_sm = dyn_sm;                  // [192][68] uints
    uint* pa_sm = dyn_sm + 192 * 68;       // [12][68] uints
    __shared__ float was[32 * 36];
    __shared__ int2  dssm[192];
    __shared__ float bas[8];
    __shared__ ull   mbar_store;

    const int t = threadIdx.x;
    const uint mbar = smem_u32(&mbar_store);
    const uint pn_base = smem_u32(pn_sm);
    const uint pa_base = smem_u32(pa_sm);

    for (int i = t; i < 1024; i += 512) {
        int k = i >> 3, c = i & 7;
        was[(k >> 2) * 36 + (k & 3) * 8 + c] = Wa[i];
    }
    if (t < 8) bas[t] = ba[t];

    const int idx64 = (((const int*)eslot)[1] != 1);
    const int e0 = blockIdx.x * 192;
    const int ag0 = blockIdx.x * 12;
    int nv = E - e0; nv = nv < 0 ? 0 : (nv > 192 ? 192 : nv);

    if (t == 0)
        asm volatile("mbarrier.init.shared.b64 [%0], 1;" :: "r"(mbar) : "memory");
    __syncthreads();
    if (t == 0) {
        uint bytes = (uint)nv * 256u + (uint)((nv + 15) >> 4) * 256u;
        asm volatile("mbarrier.arrive.expect_tx.shared.b64 _, [%0], %1;"
                     :: "r"(mbar), "r"(bytes) : "memory");
    }
    __syncthreads();

    // ---- phase 1: issue gather copies (threads 0..191, 1 edge each) -------
    if (t < nv) {
        int eg = e0 + t;
        int src, dst, slot;
        if (idx64) { src  = ((const int*)esrc)[2 * eg];
                     dst  = ((const int*)edst)[2 * eg];
                     slot = ((const int*)eslot)[2 * eg]; }
        else       { src  = ((const int*)esrc)[eg];
                     dst  = ((const int*)edst)[eg];
                     slot = ((const int*)eslot)[eg]; }
        dssm[t] = make_int2(dst, slot);
        bulk_cp(pn_base + t * 272u, (const char*)g_Pn + (size_t)src * 256, 256u, mbar);
        if ((t & 15) == 0)
            bulk_cp(pa_base + (t >> 4) * 272u, (const char*)g_Pa + (size_t)dst * 256,
                    256u, mbar);
    }
    __syncthreads();     // dssm visibility to MMA warps

    const int wid  = t >> 5;
    const int lane = t & 31;

    if (wid < 12) {
        // wait for all row copies
        asm volatile(
            "{\n\t.reg .pred P1;\n\t"
            "WAIT_%=:\n\t"
            "mbarrier.try_wait.parity.acquire.cta.shared::cta.b64 P1, [%0], 0, 0x989680;\n\t"
            "@P1 bra.uni DONE_%=;\n\t"
            "bra.uni WAIT_%=;\n\t"
            "DONE_%=:\n\t}"
            :: "r"(mbar) : "memory");

        // ---- phase 2: HMMA, 16 edges (one agent group) per warp -----------
        const int qr = lane >> 2;
        const int qc = lane & 3;
        const int m0 = wid * 16;

        uint bf0[8], bf1[8];
        const __half* wb = g_W2h + qr * 128 + 2 * qc;
#pragma unroll
        for (int s = 0; s < 8; s++) {
            bf0[s] = *(const uint*)(wb + 16 * s);
            bf1[s] = *(const uint*)(wb + 16 * s + 8);
        }

        const uint* pn0 = pn_sm + (m0 + qr) * 68;
        const uint* pn1 = pn_sm + (m0 + 8 + qr) * 68;
        const uint* paw = pa_sm + wid * 68;
        const __half2 z2 = __floats2half2_rn(0.f, 0.f);

        float d[4] = {0.f, 0.f, 0.f, 0.f};
#pragma unroll
        for (int s = 0; s < 8; s++) {
            int kq = 8 * s + qc;
            __half2 p0 = u2h(paw[kq]);
            __half2 p1 = u2h(paw[kq + 4]);
            uint a0 = h2u(__hmax2(__hadd2(u2h(pn0[kq]),     p0), z2));
            uint a1 = h2u(__hmax2(__hadd2(u2h(pn1[kq]),     p0), z2));
            uint a2 = h2u(__hmax2(__hadd2(u2h(pn0[kq + 4]), p1), z2));
            uint a3 = h2u(__hmax2(__hadd2(u2h(pn1[kq + 4]), p1), z2));
            mma16816(d, a0, a1, a2, a3, bf0[s], bf1[s]);
        }

        float2 bb = *(const float2*)(b2 + 2 * qc);
        if (m0 + qr < nv) {
            int2 ds = dssm[m0 + qr];
            *(float2*)(out + (size_t)ds.x * OUT_COLS + ds.y * 8 + 2 * qc) =
                make_float2(d[0] + bb.x, d[1] + bb.y);
        }
        if (m0 + 8 + qr < nv) {
            int2 ds = dssm[m0 + 8 + qr];
            *(float2*)(out + (size_t)ds.x * OUT_COLS + ds.y * 8 + 2 * qc) =
                make_float2(d[2] + bb.x, d[3] + bb.y);
        }
    } else {
        const int tz = t - 384;          // 0..127
        // ---- zero out[:,128:256) for the block's 12 agents ----------------
        {
            float4 z = make_float4(0.f, 0.f, 0.f, 0.f);
#pragma unroll
            for (int i = tz; i < 384; i += 128) {
                int a = ag0 + (i >> 5);
                if (a < Na)
                    *(float4*)(out + (size_t)a * OUT_COLS + 128 + (i & 31) * 4) = z;
            }
        }
        // ---- own scores: 8 threads per agent ------------------------------
        if (tz < 96) {
            int a  = ag0 + (tz >> 3);
            int jj = tz & 7;
            if (a < Na) {
                const float4* xr4 = (const float4*)(xa + (size_t)a * 128);
                float4 a4[4];
#pragma unroll
                for (int i = 0; i < 4; i++) a4[i] = xr4[jj + 8 * i];

                ull acc[4] = {0ull, 0ull, 0ull, 0ull};
#pragma unroll
                for (int i = 0; i < 4; i++) {
                    const float* wbp = was + (jj + 8 * i) * 36;
#pragma unroll
                    for (int q = 0; q < 4; q++) {
                        float v = (q == 0) ? a4[i].x : (q == 1) ? a4[i].y
                                : (q == 2) ? a4[i].z : a4[i].w;
                        ull vv = pack2(v, v);
                        const ull* w = (const ull*)(wbp + q * 8);
                        ffma2(acc[0], vv, w[0]);
                        ffma2(acc[1], vv, w[1]);
                        ffma2(acc[2], vv, w[2]);
                        ffma2(acc[3], vv, w[3]);
                    }
                }
#pragma unroll
                for (int dd = 1; dd < 8; dd <<= 1) {
#pragma unroll
                    for (int p = 0; p < 4; p++)
                        acc[p] = add2(acc[p], __shfl_xor_sync(0xffffffffu, acc[p], dd));
                }
                float2 u = unpack2(acc[jj >> 1]);
                float s = ((jj & 1) ? u.y : u.x) + bas[jj];
                out[(size_t)a * OUT_COLS + 256 + jj] = s;
            }
        }
    }
}

// ---------------------------------------------------------------------------
extern "C" void kernel_launch(void* const* d_in, const int* in_sizes, int n_in,
                              void* d_out, int out_size)
{
    const float* x_nbr   = (const float*)d_in[0];
    const float* x_agent = (const float*)d_in[1];
    const float* W1      = (const float*)d_in[2];
    const float* b1      = (const float*)d_in[3];
    const float* W2      = (const float*)d_in[4];
    const float* b2      = (const float*)d_in[5];
    const float* Wa      = (const float*)d_in[6];
    const float* ba      = (const float*)d_in[7];
    const void*  esrc    = d_in[8];
    const void*  edst    = d_in[9];
    const void*  eslot   = d_in[10];

    int Nn = in_sizes[0] / HID;
    int Na = in_sizes[1] / HID;
    int E  = in_sizes[8];
    float* out = (float*)d_out;

    const int gemm_smem = (128 + 64) * 136 * 2;          // 52224 B
    cudaFuncSetAttribute(gemm_x128, cudaFuncAttributeMaxDynamicSharedMemorySize,
                         gemm_smem);
    const int edge_smem = (192 + 12) * 68 * 4;           // 55488 B dynamic
    cudaFuncSetAttribute(edge_fused_kernel,
                         cudaFuncAttributeMaxDynamicSharedMemorySize, edge_smem);

    convert_weights<<<128, 256>>>(W1, W2);

    int Nmax = Nn > Na ? Nn : Na;
    dim3 ggrid((Nmax + 63) / 64, 2);
    gemm_x128<<<ggrid, 256, gemm_smem>>>(x_nbr, x_agent, b1, Nn, Na);

    int blocks_e = (E + 191) / 192;
    int blocks_a = (Na + 11) / 12;
    int blocks = blocks_e > blocks_a ? blocks_e : blocks_a;
    edge_fused_kernel<<<blocks, 512, edge_smem>>>(b2, Wa, ba, x_agent,
                                                  esrc, edst, eslot, out, E, Na);
}